// round 9
// baseline (speedup 1.0000x reference)
#include <cuda_runtime.h>
#include <cuda_bf16.h>
#include <math.h>
#include <cstdint>

#define BB 16
#define KK 256
#define ZZ 128
#define HH 128
#define M2P 384   // padded rows per batch in g_m2x: 256 m2z rows + 128 pair-max rows

typedef unsigned short ushortt;

// Scratch (allocation-free rule: __device__ globals)
__device__ float  g_m1 [BB*KK*ZZ];    // m1z (f32, read by k2)
__device__ float  g_m2x[BB*M2P*ZZ];   // rows 0..255: m2z ; rows 256..383: pair-max
__device__ float  g_p  [2*BB*KK*HH];  // kt3 split-K partials
// bf16 hi/lo pre-split operands
__device__ ushortt g_zh [BB*KK*ZZ], g_zl [BB*KK*ZZ];
__device__ ushortt g_mh [BB*KK*ZZ], g_ml [BB*KK*ZZ];
__device__ ushortt g_w1h[ZZ*ZZ],    g_w1l[ZZ*ZZ];
__device__ ushortt g_w2h[ZZ*ZZ],    g_w2l[ZZ*ZZ];
__device__ ushortt g_wuh[HH*2*ZZ],  g_wul[HH*2*ZZ];

// ===========================================================================
// mma.sync bf16 infrastructure (arch-stable sm_80+, assembles at compute_103)
// Tile: 32 rows x 128 cols, K=128 chunk resident as bf16 hi+lo. 256 threads.
// ===========================================================================
#define LDH 136                           // smem halves stride (272 B, ldmatrix conflict-free)
#define OFF_BIAS 0                        // 512 B
#define OFF_AHI  512                      // 32 x 272 B = 8704
#define OFF_ALO  (OFF_AHI + 32*LDH*2)
#define OFF_BHI  (OFF_ALO + 32*LDH*2)     // 128 x 272 B = 34816
#define OFF_BLO  (OFF_BHI + 128*LDH*2)
#define SMEM_BYTES (OFF_BLO + 128*LDH*2)  // 87552 B -> 2 CTAs/SM

__device__ __forceinline__ uint32_t smem_to_u32(const void* p){
    uint32_t a;
    asm("{ .reg .u64 t; cvta.to.shared.u64 t, %1; cvt.u32.u64 %0, t; }"
        : "=r"(a) : "l"(p));
    return a;
}
__device__ __forceinline__ void ldsm4(uint32_t* r, uint32_t a){
    asm volatile("ldmatrix.sync.aligned.m8n8.x4.shared.b16 {%0,%1,%2,%3}, [%4];"
        : "=r"(r[0]), "=r"(r[1]), "=r"(r[2]), "=r"(r[3]) : "r"(a));
}
__device__ __forceinline__ void mma16816(float* c, const uint32_t* a, const uint32_t* b){
    asm volatile(
        "mma.sync.aligned.m16n8k16.row.col.f32.bf16.bf16.f32 "
        "{%0,%1,%2,%3}, {%4,%5,%6,%7}, {%8,%9}, {%0,%1,%2,%3};"
        : "+f"(c[0]), "+f"(c[1]), "+f"(c[2]), "+f"(c[3])
        : "r"(a[0]), "r"(a[1]), "r"(a[2]), "r"(a[3]), "r"(b[0]), "r"(b[1]));
}
#define CP16(dst, src) \
    asm volatile("cp.async.cg.shared.global [%0], [%1], 16;" \
                 :: "r"(dst), "l"(src) : "memory")
#define CP_COMMIT() asm volatile("cp.async.commit_group;" ::: "memory")
#define CP_WAIT0()  asm volatile("cp.async.wait_group 0;"  ::: "memory")

// f32x4 -> bf16 hi/lo packed pairs
__device__ __forceinline__ void split4(float4 v, uint2 &hv, uint2 &lv){
    __nv_bfloat162 h0 = __floats2bfloat162_rn(v.x, v.y);
    __nv_bfloat162 h1 = __floats2bfloat162_rn(v.z, v.w);
    float l0 = v.x - __bfloat162float(h0.x);
    float l1 = v.y - __bfloat162float(h0.y);
    float l2 = v.z - __bfloat162float(h1.x);
    float l3 = v.w - __bfloat162float(h1.y);
    __nv_bfloat162 g0 = __floats2bfloat162_rn(l0, l1);
    __nv_bfloat162 g1 = __floats2bfloat162_rn(l2, l3);
    hv.x = *(uint32_t*)&h0; hv.y = *(uint32_t*)&h1;
    lv.x = *(uint32_t*)&g0; lv.y = *(uint32_t*)&g1;
}

// Async-copy a rows x 128-half bf16 tile (hi+lo) into padded smem.
__device__ __forceinline__ void stage_async(
    const ushortt* __restrict__ gh, const ushortt* __restrict__ gl,
    int ldg, int rows, uint32_t off_hi, uint32_t off_lo,
    uint32_t sb, int tid)
{
    const int chunks = rows * 16;                 // 16 x 16B per row
    for (int f = tid; f < chunks; f += 256){
        int r = f >> 4, c = f & 15;
        uint32_t dh = sb + off_hi + (uint32_t)r * (LDH*2) + c*16;
        uint32_t dl = sb + off_lo + (uint32_t)r * (LDH*2) + c*16;
        CP16(dh, (const void*)(gh + (size_t)r * ldg + c*8));
        CP16(dl, (const void*)(gl + (size_t)r * ldg + c*8));
    }
}

// 8 k-steps; 8 warps: wr = wid>>2 (16 rows), wc = wid&3 (32 cols).
// acc[4][4] accumulates split terms AhBh + AlBh + AhBl.
__device__ __forceinline__ void compute_chunk8(
    uint32_t sb, int wr, int wc, int lane, float acc[4][4])
{
    #pragma unroll
    for (int ks = 0; ks < 8; ks++){
        const int k0 = ks * 16;
        uint32_t ah[4], al[4];
        {
            int arow = wr*16 + (lane & 15);
            int acol = k0 + 8*(lane >> 4);
            uint32_t aoff = (uint32_t)(arow * LDH + acol) * 2u;
            ldsm4(ah, sb + OFF_AHI + aoff);
            ldsm4(al, sb + OFF_ALO + aoff);
        }
        uint32_t bh[4][2], bl[4][2];
        #pragma unroll
        for (int p = 0; p < 2; p++){
            int brow = wc*32 + p*16 + (lane & 7) + ((lane >> 4) & 1)*8;
            int bcol = k0 + ((lane >> 3) & 1)*8;
            uint32_t boff = (uint32_t)(brow * LDH + bcol) * 2u;
            uint32_t r[4];
            ldsm4(r, sb + OFF_BHI + boff);
            bh[2*p  ][0] = r[0]; bh[2*p  ][1] = r[1];
            bh[2*p+1][0] = r[2]; bh[2*p+1][1] = r[3];
            ldsm4(r, sb + OFF_BLO + boff);
            bl[2*p  ][0] = r[0]; bl[2*p  ][1] = r[1];
            bl[2*p+1][0] = r[2]; bl[2*p+1][1] = r[3];
        }
        #pragma unroll
        for (int t = 0; t < 4; t++){
            mma16816(acc[t], ah, bh[t]);
            mma16816(acc[t], al, bh[t]);
            mma16816(acc[t], ah, bl[t]);
        }
    }
}

// ---------------------------------------------------------------------------
// KPREP: split z, W1, W2, Wu into bf16 hi/lo globals. 147456 float4 total.
// ---------------------------------------------------------------------------
__global__ __launch_bounds__(256) void kprep(
    const float* __restrict__ z,  const float* __restrict__ W1,
    const float* __restrict__ W2, const float* __restrict__ Wu)
{
    int t = blockIdx.x * 256 + threadIdx.x;
    const float* src; ushortt *dh, *dl; int off;
    if      (t < 131072){ src = z;  dh = g_zh;  dl = g_zl;  off = t; }
    else if (t < 135168){ src = W1; dh = g_w1h; dl = g_w1l; off = t - 131072; }
    else if (t < 139264){ src = W2; dh = g_w2h; dl = g_w2l; off = t - 135168; }
    else                { src = Wu; dh = g_wuh; dl = g_wul; off = t - 139264; }
    float4 v = ((const float4*)src)[off];
    uint2 hv, lv; split4(v, hv, lv);
    ((uint2*)dh)[off] = hv;
    ((uint2*)dl)[off] = lv;
}

// ---------------------------------------------------------------------------
// KT1: m{1,2}z = z @ W{1,2}^T + b.  grid (128 rowtiles, 2 mats), 256 thr.
// ---------------------------------------------------------------------------
__global__ __launch_bounds__(256) void kt1_gemm(
    const float* __restrict__ b1, const float* __restrict__ b2)
{
    extern __shared__ __align__(16) char sm[];
    const uint32_t sb = smem_to_u32(sm);
    const int tid  = threadIdx.x;
    const int wid  = tid >> 5, lane = tid & 31;
    const int wr   = wid >> 2, wc = wid & 3;
    const int row0 = blockIdx.x * 32;
    const int mat  = blockIdx.y;
    const ushortt* Bh = mat ? g_w2h : g_w1h;
    const ushortt* Bl = mat ? g_w2l : g_w1l;
    const float*   b  = mat ? b2 : b1;

    if (tid < 128) ((float*)(sm + OFF_BIAS))[tid] = __ldg(&b[tid]);
    stage_async(g_zh + (size_t)row0 * ZZ, g_zl + (size_t)row0 * ZZ,
                ZZ, 32, OFF_AHI, OFF_ALO, sb, tid);
    stage_async(Bh, Bl, ZZ, 128, OFF_BHI, OFF_BLO, sb, tid);
    CP_COMMIT(); CP_WAIT0();
    __syncthreads();

    float acc[4][4];
    #pragma unroll
    for (int t = 0; t < 4; t++)
        #pragma unroll
        for (int c = 0; c < 4; c++) acc[t][c] = 0.f;

    compute_chunk8(sb, wr, wc, lane, acc);

    const float* bias = (const float*)(sm + OFF_BIAS);
    #pragma unroll
    for (int t = 0; t < 4; t++){
        int gn  = wc*32 + t*8 + (lane & 3)*2;
        int rlo = row0 + wr*16 + (lane >> 2);
        float bx = bias[gn], by = bias[gn+1];
        float2 v0 = make_float2(acc[t][0] + bx, acc[t][1] + by);
        float2 v1 = make_float2(acc[t][2] + bx, acc[t][3] + by);
        if (mat == 0){
            *(float2*)(g_m1 + (size_t)rlo * ZZ + gn)       = v0;
            *(float2*)(g_m1 + (size_t)(rlo + 8) * ZZ + gn) = v1;
        } else {
            int b0 = rlo >> 8,       i0 = rlo & 255;
            int b8 = (rlo + 8) >> 8, i8 = (rlo + 8) & 255;
            *(float2*)(g_m2x + ((size_t)b0 * M2P + i0) * ZZ + gn) = v0;
            *(float2*)(g_m2x + ((size_t)b8 * M2P + i8) * ZZ + gn) = v1;
        }
    }
}

// ---------------------------------------------------------------------------
// K2a: pair-max rows: g_m2x[b][256+jp] = max(g_m2x[b][2jp], g_m2x[b][2jp+1])
// ---------------------------------------------------------------------------
__global__ __launch_bounds__(256) void k2a_pairmax()
{
    int t  = blockIdx.x * 256 + threadIdx.x;     // 0..65535
    int b  = t >> 12;
    int r  = t & 4095;
    int jp = r >> 5;
    int q  = r & 31;
    const float4* rows = (const float4*)g_m2x;
    float4 a = rows[((size_t)b * M2P + 2*jp    ) * 32 + q];
    float4 c = rows[((size_t)b * M2P + 2*jp + 1) * 32 + q];
    float4 m;
    m.x = fmaxf(a.x, c.x); m.y = fmaxf(a.y, c.y);
    m.z = fmaxf(a.z, c.z); m.w = fmaxf(a.w, c.w);
    ((float4*)g_m2x)[((size_t)b * M2P + 256 + jp) * 32 + q] = m;
}

// ---------------------------------------------------------------------------
// K2: m[b,i,:] = relu(m1z[b,i,:] + max_{j in N(i)} m2z[b,j,:]).
// Warp = one i. Pair-collapsed neighbor list, unroll-8 MLP loop.
// Writes m directly as bf16 hi/lo (consumed only by kt3).
// ---------------------------------------------------------------------------
__global__ __launch_bounds__(512) void k2_maxmsg(const int* __restrict__ P)
{
    __shared__ int PsT[16][257];
    __shared__ unsigned short lists[16][128];
    const int b   = blockIdx.y;
    const int i0  = blockIdx.x * 16;
    const int tid = threadIdx.x;

    for (int idx = tid; idx < KK * 16; idx += 512) {
        int j = idx >> 4, il = idx & 15;
        PsT[il][j] = P[(b * KK + j) * KK + i0 + il];
    }
    __syncthreads();

    const int w    = tid >> 5;
    const int lane = tid & 31;

    int cnt = 0;
    #pragma unroll
    for (int jb = 0; jb < 128; jb += 32) {
        int jp = jb + lane;
        int f0 = PsT[w][2*jp];
        int f1 = PsT[w][2*jp + 1];
        int present = (f0 | f1) != 0;
        int idx = (f0 && f1) ? (256 + jp) : (f0 ? 2*jp : 2*jp + 1);
        unsigned bal = __ballot_sync(0xffffffffu, present);
        if (present) {
            int pos = cnt + __popc(bal & ((1u << lane) - 1u));
            lists[w][pos] = (unsigned short)idx;
        }
        cnt += __popc(bal);
    }
    __syncwarp();

    const float* base = g_m2x + (size_t)b * M2P * ZZ + lane * 4;
    float4 acc = make_float4(-INFINITY, -INFINITY, -INFINITY, -INFINITY);

    int e = 0;
    for (; e + 8 <= cnt; e += 8) {
        ushort4 ja = *(const ushort4*)&lists[w][e];
        ushort4 jb = *(const ushort4*)&lists[w][e + 4];
        float4 v0 = *(const float4*)(base + (int)ja.x * ZZ);
        float4 v1 = *(const float4*)(base + (int)ja.y * ZZ);
        float4 v2 = *(const float4*)(base + (int)ja.z * ZZ);
        float4 v3 = *(const float4*)(base + (int)ja.w * ZZ);
        float4 v4 = *(const float4*)(base + (int)jb.x * ZZ);
        float4 v5 = *(const float4*)(base + (int)jb.y * ZZ);
        float4 v6 = *(const float4*)(base + (int)jb.z * ZZ);
        float4 v7 = *(const float4*)(base + (int)jb.w * ZZ);
        acc.x = fmaxf(acc.x, fmaxf(fmaxf(fmaxf(v0.x,v1.x),fmaxf(v2.x,v3.x)),
                                   fmaxf(fmaxf(v4.x,v5.x),fmaxf(v6.x,v7.x))));
        acc.y = fmaxf(acc.y, fmaxf(fmaxf(fmaxf(v0.y,v1.y),fmaxf(v2.y,v3.y)),
                                   fmaxf(fmaxf(v4.y,v5.y),fmaxf(v6.y,v7.y))));
        acc.z = fmaxf(acc.z, fmaxf(fmaxf(fmaxf(v0.z,v1.z),fmaxf(v2.z,v3.z)),
                                   fmaxf(fmaxf(v4.z,v5.z),fmaxf(v6.z,v7.z))));
        acc.w = fmaxf(acc.w, fmaxf(fmaxf(fmaxf(v0.w,v1.w),fmaxf(v2.w,v3.w)),
                                   fmaxf(fmaxf(v4.w,v5.w),fmaxf(v6.w,v7.w))));
    }
    for (; e + 4 <= cnt; e += 4) {
        ushort4 jj = *(const ushort4*)&lists[w][e];
        float4 v0 = *(const float4*)(base + (int)jj.x * ZZ);
        float4 v1 = *(const float4*)(base + (int)jj.y * ZZ);
        float4 v2 = *(const float4*)(base + (int)jj.z * ZZ);
        float4 v3 = *(const float4*)(base + (int)jj.w * ZZ);
        acc.x = fmaxf(fmaxf(fmaxf(acc.x, v0.x), fmaxf(v1.x, v2.x)), v3.x);
        acc.y = fmaxf(fmaxf(fmaxf(acc.y, v0.y), fmaxf(v1.y, v2.y)), v3.y);
        acc.z = fmaxf(fmaxf(fmaxf(acc.z, v0.z), fmaxf(v1.z, v2.z)), v3.z);
        acc.w = fmaxf(fmaxf(fmaxf(acc.w, v0.w), fmaxf(v1.w, v2.w)), v3.w);
    }
    for (; e < cnt; e++) {
        int j = lists[w][e];
        float4 v = *(const float4*)(base + j * ZZ);
        acc.x = fmaxf(acc.x, v.x);
        acc.y = fmaxf(acc.y, v.y);
        acc.z = fmaxf(acc.z, v.z);
        acc.w = fmaxf(acc.w, v.w);
    }

    const size_t pos = ((size_t)b * KK + i0 + w) * ZZ + lane * 4;
    float4 m1 = *(const float4*)(g_m1 + pos);
    float4 m;
    m.x = fmaxf(m1.x + acc.x, 0.f);
    m.y = fmaxf(m1.y + acc.y, 0.f);
    m.z = fmaxf(m1.z + acc.z, 0.f);
    m.w = fmaxf(m1.w + acc.w, 0.f);
    uint2 hv, lv; split4(m, hv, lv);
    *(uint2*)(g_mh + pos) = hv;
    *(uint2*)(g_ml + pos) = lv;
}

// ---------------------------------------------------------------------------
// KT3: split-K partials. ksplit 0: z @ WuL^T ; 1: m @ WuR^T.
// grid (128 rowtiles, 2 ksplit), 256 thr.
// ---------------------------------------------------------------------------
__global__ __launch_bounds__(256) void kt3_gemm()
{
    extern __shared__ __align__(16) char sm[];
    const uint32_t sb = smem_to_u32(sm);
    const int tid  = threadIdx.x;
    const int wid  = tid >> 5, lane = tid & 31;
    const int wr   = wid >> 2, wc = wid & 3;
    const int row0 = blockIdx.x * 32;
    const int ks   = blockIdx.y;
    const ushortt* Ah = (ks ? g_mh : g_zh) + (size_t)row0 * ZZ;
    const ushortt* Al = (ks ? g_ml : g_zl) + (size_t)row0 * ZZ;
    const ushortt* Bh = g_wuh + ks * ZZ;      // Wu row length 256 halves
    const ushortt* Bl = g_wul + ks * ZZ;

    stage_async(Ah, Al, ZZ, 32, OFF_AHI, OFF_ALO, sb, tid);
    stage_async(Bh, Bl, 2 * ZZ, 128, OFF_BHI, OFF_BLO, sb, tid);
    CP_COMMIT(); CP_WAIT0();
    __syncthreads();

    float acc[4][4];
    #pragma unroll
    for (int t = 0; t < 4; t++)
        #pragma unroll
        for (int c = 0; c < 4; c++) acc[t][c] = 0.f;

    compute_chunk8(sb, wr, wc, lane, acc);

    float* dst = g_p + (size_t)ks * (BB * KK * HH);
    #pragma unroll
    for (int t = 0; t < 4; t++){
        int gn  = wc*32 + t*8 + (lane & 3)*2;
        int rlo = row0 + wr*16 + (lane >> 2);
        *(float2*)(dst + (size_t)rlo * HH + gn)       = make_float2(acc[t][0], acc[t][1]);
        *(float2*)(dst + (size_t)(rlo + 8) * HH + gn) = make_float2(acc[t][2], acc[t][3]);
    }
}

// ---------------------------------------------------------------------------
// KT3 epilogue: out = relu(p0 + p1 + bu), float4-vectorized.
// ---------------------------------------------------------------------------
__global__ __launch_bounds__(256) void k3_epi(
    const float* __restrict__ bu, float* __restrict__ out)
{
    int t = blockIdx.x * 256 + threadIdx.x;      // 0..131071 (float4 lanes)
    const float4* p4 = (const float4*)g_p;
    float4 a = p4[t];
    float4 c = p4[(BB * KK * HH / 4) + t];
    float4 bb = __ldg(&((const float4*)bu)[t & 31]);
    float4 o;
    o.x = fmaxf(a.x + c.x + bb.x, 0.f);
    o.y = fmaxf(a.y + c.y + bb.y, 0.f);
    o.z = fmaxf(a.z + c.z + bb.z, 0.f);
    o.w = fmaxf(a.w + c.w + bb.w, 0.f);
    ((float4*)out)[t] = o;
}

// ---------------------------------------------------------------------------
extern "C" void kernel_launch(void* const* d_in, const int* in_sizes, int n_in,
                              void* d_out, int out_size)
{
    const float* z  = (const float*)d_in[0];
    const int*   P  = (const int*)  d_in[1];
    const float* W1 = (const float*)d_in[2];
    const float* b1 = (const float*)d_in[3];
    const float* W2 = (const float*)d_in[4];
    const float* b2 = (const float*)d_in[5];
    const float* Wu = (const float*)d_in[6];
    const float* bu = (const float*)d_in[7];
    float* out = (float*)d_out;

    cudaFuncSetAttribute(kt1_gemm, cudaFuncAttributeMaxDynamicSharedMemorySize, SMEM_BYTES);
    cudaFuncSetAttribute(kt3_gemm, cudaFuncAttributeMaxDynamicSharedMemorySize, SMEM_BYTES);

    kprep<<<576, 256>>>(z, W1, W2, Wu);
    kt1_gemm<<<dim3(BB * KK / 32, 2), 256, SMEM_BYTES>>>(b1, b2);
    k2a_pairmax<<<256, 256>>>();
    k2_maxmsg<<<dim3(KK / 16, BB), 512>>>(P);
    kt3_gemm<<<dim3(BB * KK / 32, 2), 256, SMEM_BYTES>>>();
    k3_epi<<<BB * KK * HH / 4 / 256, 256>>>(bu, out);
}

// round 13
// speedup vs baseline: 1.2236x; 1.2236x over previous
#include <cuda_runtime.h>
#include <cuda_bf16.h>
#include <math.h>
#include <cstdint>

#define BB 16
#define KK 256
#define ZZ 128
#define HH 128
#define M2P 384   // padded rows per batch in g_m2x: 256 m2z rows + 128 pair-max rows

// Scratch (allocation-free rule: __device__ globals)
__device__ float g_m1 [BB*KK*ZZ];    // m1z
__device__ float g_m2x[BB*M2P*ZZ];   // rows 0..255: m2z ; rows 256..383: pair-max
__device__ float g_m  [BB*KK*ZZ];    // relu(m1z + masked max)
__device__ float g_p  [BB*KK*HH];    // p0 = z @ WuL^T partial

// ===========================================================================
// mma.sync bf16 GEMM infrastructure (arch-stable: sm_80+, works at compute_103)
// Tile: 32 rows x 128 cols, K=128 chunk resident as bf16 hi+lo. 128 threads.
// ===========================================================================
#define LDH 136            // smem stride in halves (128 + 8 pad -> ldmatrix conflict-free)
#define OFF_BIAS 0                        // 512 B
#define OFF_AHI  512                      // 32 x 136 halves = 8704 B
#define OFF_ALO  (OFF_AHI + 32*LDH*2)
#define OFF_BHI  (OFF_ALO + 32*LDH*2)     // 128 x 136 halves = 34816 B
#define OFF_BLO  (OFF_BHI + 128*LDH*2)
#define SMEM_BYTES (OFF_BLO + 128*LDH*2)  // 87552 B -> 2 CTAs/SM

__device__ __forceinline__ uint32_t smem_to_u32(const void* p){
    uint32_t a;
    asm("{ .reg .u64 t; cvta.to.shared.u64 t, %1; cvt.u32.u64 %0, t; }"
        : "=r"(a) : "l"(p));
    return a;
}
__device__ __forceinline__ void ldsm4(uint32_t* r, uint32_t a){
    asm volatile("ldmatrix.sync.aligned.m8n8.x4.shared.b16 {%0,%1,%2,%3}, [%4];"
        : "=r"(r[0]), "=r"(r[1]), "=r"(r[2]), "=r"(r[3]) : "r"(a));
}
__device__ __forceinline__ void mma16816(float* c, const uint32_t* a, const uint32_t* b){
    asm volatile(
        "mma.sync.aligned.m16n8k16.row.col.f32.bf16.bf16.f32 "
        "{%0,%1,%2,%3}, {%4,%5,%6,%7}, {%8,%9}, {%0,%1,%2,%3};"
        : "+f"(c[0]), "+f"(c[1]), "+f"(c[2]), "+f"(c[3])
        : "r"(a[0]), "r"(a[1]), "r"(a[2]), "r"(a[3]), "r"(b[0]), "r"(b[1]));
}

// Stage rows x 128 f32 tile -> bf16 hi + lo, row-major [row][LDH] halves.
__device__ __forceinline__ void stage_rows(
    const float* __restrict__ src, int ldf, int rows,
    char* sm, int off_hi, int off_lo, int tid)
{
    for (int f = tid; f < rows * 32; f += 128){
        int r  = f >> 5;
        int c4 = f & 31;
        float4 v = *(const float4*)(src + (size_t)r * ldf + 4*c4);
        __nv_bfloat162 h0 = __floats2bfloat162_rn(v.x, v.y);
        __nv_bfloat162 h1 = __floats2bfloat162_rn(v.z, v.w);
        float l0 = v.x - __bfloat162float(h0.x);
        float l1 = v.y - __bfloat162float(h0.y);
        float l2 = v.z - __bfloat162float(h1.x);
        float l3 = v.w - __bfloat162float(h1.y);
        __nv_bfloat162 g0 = __floats2bfloat162_rn(l0, l1);
        __nv_bfloat162 g1 = __floats2bfloat162_rn(l2, l3);
        uint32_t byt = (uint32_t)(r * LDH + 4*c4) * 2u;
        uint2 hv; hv.x = *(uint32_t*)&h0; hv.y = *(uint32_t*)&h1;
        uint2 lv; lv.x = *(uint32_t*)&g0; lv.y = *(uint32_t*)&g1;
        *(uint2*)(sm + off_hi + byt) = hv;
        *(uint2*)(sm + off_lo + byt) = lv;
    }
}

// 8 k-steps over the staged K=128 chunk; warp tile 16 rows x 64 cols.
// 4 warps: wr = wid>>1 (0..1), wc = wid&1 (0..1).
// acc[8][4] accumulates split terms: AhBh + AlBh + AhBl.
__device__ __forceinline__ void compute_chunk(
    uint32_t sb, int wr, int wc, int lane, float acc[8][4])
{
    #pragma unroll
    for (int ks = 0; ks < 8; ks++){
        const int k0 = ks * 16;
        uint32_t ah[4], al[4];
        {
            int arow = wr*16 + (lane & 15);
            int acol = k0 + 8*(lane >> 4);
            uint32_t aoff = (uint32_t)(arow * LDH + acol) * 2u;
            ldsm4(ah, sb + OFF_AHI + aoff);
            ldsm4(al, sb + OFF_ALO + aoff);
        }
        uint32_t bh[8][2], bl[8][2];
        #pragma unroll
        for (int p = 0; p < 4; p++){
            int brow = wc*64 + p*16 + (lane & 7) + ((lane >> 4) & 1)*8;
            int bcol = k0 + ((lane >> 3) & 1)*8;
            uint32_t boff = (uint32_t)(brow * LDH + bcol) * 2u;
            uint32_t r[4];
            ldsm4(r, sb + OFF_BHI + boff);
            bh[2*p  ][0] = r[0]; bh[2*p  ][1] = r[1];
            bh[2*p+1][0] = r[2]; bh[2*p+1][1] = r[3];
            ldsm4(r, sb + OFF_BLO + boff);
            bl[2*p  ][0] = r[0]; bl[2*p  ][1] = r[1];
            bl[2*p+1][0] = r[2]; bl[2*p+1][1] = r[3];
        }
        #pragma unroll
        for (int t = 0; t < 8; t++){
            mma16816(acc[t], ah, bh[t]);
            mma16816(acc[t], al, bh[t]);
            mma16816(acc[t], ah, bl[t]);
        }
    }
}

// ---------------------------------------------------------------------------
// K_A: uber-GEMM. grid (128 rowtiles, 3 mats), 128 thr.
//   mat 0: m1z = z @ W1^T + b1          -> g_m1
//   mat 1: m2z = z @ W2^T + b2          -> g_m2x  (+ fused pair-max rows)
//   mat 2: p0  = z @ WuL^T  (no bias)   -> g_p
// mat 2 is independent of k2 and overlaps mats 0/1 in the same wave.
// ---------------------------------------------------------------------------
__global__ __launch_bounds__(128) void kA_gemm(
    const float* __restrict__ z,
    const float* __restrict__ W1, const float* __restrict__ b1,
    const float* __restrict__ W2, const float* __restrict__ b2,
    const float* __restrict__ Wu)
{
    extern __shared__ __align__(16) char sm[];
    const uint32_t sb = smem_to_u32(sm);
    const int tid  = threadIdx.x;
    const int wid  = tid >> 5, lane = tid & 31;
    const int wr   = wid >> 1, wc = wid & 1;
    const int row0 = blockIdx.x * 32;
    const int mat  = blockIdx.y;

    const float* W;  int ldw;
    if      (mat == 0){ W = W1; ldw = ZZ; }
    else if (mat == 1){ W = W2; ldw = ZZ; }
    else              { W = Wu; ldw = 2 * ZZ; }   // WuL = Wu[:, 0:128]

    float bias_v = 0.f;
    if (mat == 0) bias_v = __ldg(&b1[tid]);
    else if (mat == 1) bias_v = __ldg(&b2[tid]);
    ((float*)(sm + OFF_BIAS))[tid] = bias_v;

    stage_rows(z + (size_t)row0 * ZZ, ZZ, 32, sm, OFF_AHI, OFF_ALO, tid);
    stage_rows(W, ldw, 128, sm, OFF_BHI, OFF_BLO, tid);
    __syncthreads();

    float acc[8][4];
    #pragma unroll
    for (int t = 0; t < 8; t++)
        #pragma unroll
        for (int c = 0; c < 4; c++) acc[t][c] = 0.f;

    compute_chunk(sb, wr, wc, lane, acc);

    const float* bias = (const float*)(sm + OFF_BIAS);
    #pragma unroll
    for (int t = 0; t < 8; t++){
        int gn   = wc*64 + t*8 + (lane & 3)*2;
        int rlo  = row0 + wr*16 + (lane >> 2);
        float bx = bias[gn], by = bias[gn+1];
        float2 v0 = make_float2(acc[t][0] + bx, acc[t][1] + by);
        float2 v1 = make_float2(acc[t][2] + bx, acc[t][3] + by);
        if (mat == 0){
            *(float2*)(g_m1 + (size_t)rlo * ZZ + gn)       = v0;
            *(float2*)(g_m1 + (size_t)(rlo + 8) * ZZ + gn) = v1;
        } else if (mat == 1){
            int b0 = rlo >> 8,       i0 = rlo & 255;
            int b8 = (rlo + 8) >> 8, i8 = (rlo + 8) & 255;
            *(float2*)(g_m2x + ((size_t)b0 * M2P + i0) * ZZ + gn) = v0;
            *(float2*)(g_m2x + ((size_t)b8 * M2P + i8) * ZZ + gn) = v1;
        } else {
            *(float2*)(g_p + (size_t)rlo * HH + gn)       = v0;
            *(float2*)(g_p + (size_t)(rlo + 8) * HH + gn) = v1;
        }
    }

    // Fused k2a: this CTA owns 32 consecutive m2z rows = 16 complete pairs.
    if (mat == 1){
        __syncthreads();   // all m2z stores visible block-wide
        const int b   = row0 >> 8;
        const int il0 = row0 & 255;
        const float4* rows = (const float4*)g_m2x;
        #pragma unroll
        for (int f = tid; f < 512; f += 128){
            int pr = f >> 5, q = f & 31;
            int r0 = il0 + 2*pr;
            float4 a = rows[((size_t)b * M2P + r0    ) * 32 + q];
            float4 c = rows[((size_t)b * M2P + r0 + 1) * 32 + q];
            float4 m;
            m.x = fmaxf(a.x, c.x); m.y = fmaxf(a.y, c.y);
            m.z = fmaxf(a.z, c.z); m.w = fmaxf(a.w, c.w);
            ((float4*)g_m2x)[((size_t)b * M2P + 256 + (il0 >> 1) + pr) * 32 + q] = m;
        }
    }
}

// ---------------------------------------------------------------------------
// K2: m[b,i,:] = relu(m1z[b,i,:] + max_{j: P[b,j,i]!=0} m2z[b,j,:])
// Warp = one i. Pair-collapsed neighbor list, unroll-8 MLP loop.
// ---------------------------------------------------------------------------
__global__ __launch_bounds__(512) void k2_maxmsg(const int* __restrict__ P)
{
    __shared__ int PsT[16][257];
    __shared__ unsigned short lists[16][128];
    const int b   = blockIdx.y;
    const int i0  = blockIdx.x * 16;
    const int tid = threadIdx.x;

    for (int idx = tid; idx < KK * 16; idx += 512) {
        int j = idx >> 4, il = idx & 15;
        PsT[il][j] = P[(b * KK + j) * KK + i0 + il];
    }
    __syncthreads();

    const int w    = tid >> 5;
    const int lane = tid & 31;

    int cnt = 0;
    #pragma unroll
    for (int jb = 0; jb < 128; jb += 32) {
        int jp = jb + lane;
        int f0 = PsT[w][2*jp];
        int f1 = PsT[w][2*jp + 1];
        int present = (f0 | f1) != 0;
        int idx = (f0 && f1) ? (256 + jp) : (f0 ? 2*jp : 2*jp + 1);
        unsigned bal = __ballot_sync(0xffffffffu, present);
        if (present) {
            int pos = cnt + __popc(bal & ((1u << lane) - 1u));
            lists[w][pos] = (unsigned short)idx;
        }
        cnt += __popc(bal);
    }
    __syncwarp();

    const float* base = g_m2x + (size_t)b * M2P * ZZ + lane * 4;
    float4 acc = make_float4(-INFINITY, -INFINITY, -INFINITY, -INFINITY);

    int e = 0;
    for (; e + 8 <= cnt; e += 8) {
        ushort4 ja = *(const ushort4*)&lists[w][e];
        ushort4 jb = *(const ushort4*)&lists[w][e + 4];
        float4 v0 = *(const float4*)(base + (int)ja.x * ZZ);
        float4 v1 = *(const float4*)(base + (int)ja.y * ZZ);
        float4 v2 = *(const float4*)(base + (int)ja.z * ZZ);
        float4 v3 = *(const float4*)(base + (int)ja.w * ZZ);
        float4 v4 = *(const float4*)(base + (int)jb.x * ZZ);
        float4 v5 = *(const float4*)(base + (int)jb.y * ZZ);
        float4 v6 = *(const float4*)(base + (int)jb.z * ZZ);
        float4 v7 = *(const float4*)(base + (int)jb.w * ZZ);
        acc.x = fmaxf(acc.x, fmaxf(fmaxf(fmaxf(v0.x,v1.x),fmaxf(v2.x,v3.x)),
                                   fmaxf(fmaxf(v4.x,v5.x),fmaxf(v6.x,v7.x))));
        acc.y = fmaxf(acc.y, fmaxf(fmaxf(fmaxf(v0.y,v1.y),fmaxf(v2.y,v3.y)),
                                   fmaxf(fmaxf(v4.y,v5.y),fmaxf(v6.y,v7.y))));
        acc.z = fmaxf(acc.z, fmaxf(fmaxf(fmaxf(v0.z,v1.z),fmaxf(v2.z,v3.z)),
                                   fmaxf(fmaxf(v4.z,v5.z),fmaxf(v6.z,v7.z))));
        acc.w = fmaxf(acc.w, fmaxf(fmaxf(fmaxf(v0.w,v1.w),fmaxf(v2.w,v3.w)),
                                   fmaxf(fmaxf(v4.w,v5.w),fmaxf(v6.w,v7.w))));
    }
    for (; e + 4 <= cnt; e += 4) {
        ushort4 jj = *(const ushort4*)&lists[w][e];
        float4 v0 = *(const float4*)(base + (int)jj.x * ZZ);
        float4 v1 = *(const float4*)(base + (int)jj.y * ZZ);
        float4 v2 = *(const float4*)(base + (int)jj.z * ZZ);
        float4 v3 = *(const float4*)(base + (int)jj.w * ZZ);
        acc.x = fmaxf(fmaxf(fmaxf(acc.x, v0.x), fmaxf(v1.x, v2.x)), v3.x);
        acc.y = fmaxf(fmaxf(fmaxf(acc.y, v0.y), fmaxf(v1.y, v2.y)), v3.y);
        acc.z = fmaxf(fmaxf(fmaxf(acc.z, v0.z), fmaxf(v1.z, v2.z)), v3.z);
        acc.w = fmaxf(fmaxf(fmaxf(acc.w, v0.w), fmaxf(v1.w, v2.w)), v3.w);
    }
    for (; e < cnt; e++) {
        int j = lists[w][e];
        float4 v = *(const float4*)(base + j * ZZ);
        acc.x = fmaxf(acc.x, v.x);
        acc.y = fmaxf(acc.y, v.y);
        acc.z = fmaxf(acc.z, v.z);
        acc.w = fmaxf(acc.w, v.w);
    }

    const size_t off = ((size_t)b * KK + i0 + w) * ZZ + lane * 4;
    float4 m1 = *(const float4*)(g_m1 + off);
    float4 m;
    m.x = fmaxf(m1.x + acc.x, 0.f);
    m.y = fmaxf(m1.y + acc.y, 0.f);
    m.z = fmaxf(m1.z + acc.z, 0.f);
    m.w = fmaxf(m1.w + acc.w, 0.f);
    *(float4*)(g_m + off) = m;
}

// ---------------------------------------------------------------------------
// K_B: p1 = m @ WuR^T, fused epilogue: out = relu(p0 + p1 + bu).
// grid 128 rowtiles, 128 thr.
// ---------------------------------------------------------------------------
__global__ __launch_bounds__(128) void kB_gemm(
    const float* __restrict__ Wu, const float* __restrict__ bu,
    float* __restrict__ out)
{
    extern __shared__ __align__(16) char sm[];
    const uint32_t sb = smem_to_u32(sm);
    const int tid  = threadIdx.x;
    const int wid  = tid >> 5, lane = tid & 31;
    const int wr   = wid >> 1, wc = wid & 1;
    const int row0 = blockIdx.x * 32;

    ((float*)(sm + OFF_BIAS))[tid] = __ldg(&bu[tid]);
    stage_rows(g_m + (size_t)row0 * ZZ, ZZ, 32, sm, OFF_AHI, OFF_ALO, tid);
    stage_rows(Wu + ZZ, 2 * ZZ, 128, sm, OFF_BHI, OFF_BLO, tid);  // WuR
    __syncthreads();

    float acc[8][4];
    #pragma unroll
    for (int t = 0; t < 8; t++)
        #pragma unroll
        for (int c = 0; c < 4; c++) acc[t][c] = 0.f;

    compute_chunk(sb, wr, wc, lane, acc);

    const float* bias = (const float*)(sm + OFF_BIAS);
    #pragma unroll
    for (int t = 0; t < 8; t++){
        int gn  = wc*64 + t*8 + (lane & 3)*2;
        int rlo = row0 + wr*16 + (lane >> 2);
        float bx = bias[gn], by = bias[gn+1];
        float2 p0a = *(const float2*)(g_p + (size_t)rlo * HH + gn);
        float2 p0b = *(const float2*)(g_p + (size_t)(rlo + 8) * HH + gn);
        float2 v0 = make_float2(fmaxf(acc[t][0] + p0a.x + bx, 0.f),
                                fmaxf(acc[t][1] + p0a.y + by, 0.f));
        float2 v1 = make_float2(fmaxf(acc[t][2] + p0b.x + bx, 0.f),
                                fmaxf(acc[t][3] + p0b.y + by, 0.f));
        *(float2*)(out + (size_t)rlo * HH + gn)       = v0;
        *(float2*)(out + (size_t)(rlo + 8) * HH + gn) = v1;
    }
}

// ---------------------------------------------------------------------------
extern "C" void kernel_launch(void* const* d_in, const int* in_sizes, int n_in,
                              void* d_out, int out_size)
{
    const float* z  = (const float*)d_in[0];
    const int*   P  = (const int*)  d_in[1];
    const float* W1 = (const float*)d_in[2];
    const float* b1 = (const float*)d_in[3];
    const float* W2 = (const float*)d_in[4];
    const float* b2 = (const float*)d_in[5];
    const float* Wu = (const float*)d_in[6];
    const float* bu = (const float*)d_in[7];
    float* out = (float*)d_out;

    cudaFuncSetAttribute(kA_gemm, cudaFuncAttributeMaxDynamicSharedMemorySize, SMEM_BYTES);
    cudaFuncSetAttribute(kB_gemm, cudaFuncAttributeMaxDynamicSharedMemorySize, SMEM_BYTES);

    kA_gemm<<<dim3(BB * KK / 32, 3), 128, SMEM_BYTES>>>(z, W1, b1, W2, b2, Wu);
    k2_maxmsg<<<dim3(KK / 16, BB), 512>>>(P);
    kB_gemm<<<BB * KK / 32, 128, SMEM_BYTES>>>(Wu, bu, out);
}

// round 15
// speedup vs baseline: 1.2557x; 1.0262x over previous
#include <cuda_runtime.h>
#include <cuda_bf16.h>
#include <math.h>
#include <cstdint>

#define BB 16
#define KK 256
#define ZZ 128
#define HH 128
#define M2P 384   // padded rows per batch in g_m2x: 256 m2z rows + 128 pair-max rows

// Scratch (allocation-free rule: __device__ globals)
__device__ float g_m1 [BB*KK*ZZ];    // m1z
__device__ float g_m2x[BB*M2P*ZZ];   // rows 0..255: m2z ; rows 256..383: pair-max
__device__ float g_m  [BB*KK*ZZ];    // relu(m1z + masked max)
__device__ float g_p  [BB*KK*HH];    // p0 = z @ WuL^T partial

// ===========================================================================
// mma.sync bf16 GEMM infrastructure (arch-stable: sm_80+, works at compute_103)
// Tile: 32 rows x 128 cols, K=128 chunk resident as bf16 hi+lo. 256 threads.
// ===========================================================================
#define LDH 136            // smem stride in halves (128 + 8 pad -> ldmatrix conflict-free)
#define OFF_BIAS 0                        // 512 B
#define OFF_AHI  512                      // 32 x 136 halves = 8704 B
#define OFF_ALO  (OFF_AHI + 32*LDH*2)
#define OFF_BHI  (OFF_ALO + 32*LDH*2)     // 128 x 136 halves = 34816 B
#define OFF_BLO  (OFF_BHI + 128*LDH*2)
#define SMEM_BYTES (OFF_BLO + 128*LDH*2)  // 87552 B -> 2 CTAs/SM (16 warps/SM)

__device__ __forceinline__ uint32_t smem_to_u32(const void* p){
    uint32_t a;
    asm("{ .reg .u64 t; cvta.to.shared.u64 t, %1; cvt.u32.u64 %0, t; }"
        : "=r"(a) : "l"(p));
    return a;
}
__device__ __forceinline__ void ldsm4(uint32_t* r, uint32_t a){
    asm volatile("ldmatrix.sync.aligned.m8n8.x4.shared.b16 {%0,%1,%2,%3}, [%4];"
        : "=r"(r[0]), "=r"(r[1]), "=r"(r[2]), "=r"(r[3]) : "r"(a));
}
__device__ __forceinline__ void mma16816(float* c, const uint32_t* a, const uint32_t* b){
    asm volatile(
        "mma.sync.aligned.m16n8k16.row.col.f32.bf16.bf16.f32 "
        "{%0,%1,%2,%3}, {%4,%5,%6,%7}, {%8,%9}, {%0,%1,%2,%3};"
        : "+f"(c[0]), "+f"(c[1]), "+f"(c[2]), "+f"(c[3])
        : "r"(a[0]), "r"(a[1]), "r"(a[2]), "r"(a[3]), "r"(b[0]), "r"(b[1]));
}

// Stage rows x 128 f32 tile -> bf16 hi + lo, row-major [row][LDH] halves.
__device__ __forceinline__ void stage_rows(
    const float* __restrict__ src, int ldf, int rows,
    char* sm, int off_hi, int off_lo, int tid)
{
    for (int f = tid; f < rows * 32; f += 256){
        int r  = f >> 5;
        int c4 = f & 31;
        float4 v = *(const float4*)(src + (size_t)r * ldf + 4*c4);
        __nv_bfloat162 h0 = __floats2bfloat162_rn(v.x, v.y);
        __nv_bfloat162 h1 = __floats2bfloat162_rn(v.z, v.w);
        float l0 = v.x - __bfloat162float(h0.x);
        float l1 = v.y - __bfloat162float(h0.y);
        float l2 = v.z - __bfloat162float(h1.x);
        float l3 = v.w - __bfloat162float(h1.y);
        __nv_bfloat162 g0 = __floats2bfloat162_rn(l0, l1);
        __nv_bfloat162 g1 = __floats2bfloat162_rn(l2, l3);
        uint32_t byt = (uint32_t)(r * LDH + 4*c4) * 2u;
        uint2 hv; hv.x = *(uint32_t*)&h0; hv.y = *(uint32_t*)&h1;
        uint2 lv; lv.x = *(uint32_t*)&g0; lv.y = *(uint32_t*)&g1;
        *(uint2*)(sm + off_hi + byt) = hv;
        *(uint2*)(sm + off_lo + byt) = lv;
    }
}

// 8 k-steps over the staged K=128 chunk; 8 warps.
// Warp tile 16 rows x 32 cols: wr = wid>>2 (0..1), wc = wid&3 (0..3).
// acc[4][4] accumulates split terms AhBh + AlBh + AhBl.
__device__ __forceinline__ void compute_chunk8(
    uint32_t sb, int wr, int wc, int lane, float acc[4][4])
{
    #pragma unroll
    for (int ks = 0; ks < 8; ks++){
        const int k0 = ks * 16;
        uint32_t ah[4], al[4];
        {
            int arow = wr*16 + (lane & 15);
            int acol = k0 + 8*(lane >> 4);
            uint32_t aoff = (uint32_t)(arow * LDH + acol) * 2u;
            ldsm4(ah, sb + OFF_AHI + aoff);
            ldsm4(al, sb + OFF_ALO + aoff);
        }
        uint32_t bh[4][2], bl[4][2];
        #pragma unroll
        for (int p = 0; p < 2; p++){
            int brow = wc*32 + p*16 + (lane & 7) + ((lane >> 4) & 1)*8;
            int bcol = k0 + ((lane >> 3) & 1)*8;
            uint32_t boff = (uint32_t)(brow * LDH + bcol) * 2u;
            uint32_t r[4];
            ldsm4(r, sb + OFF_BHI + boff);
            bh[2*p  ][0] = r[0]; bh[2*p  ][1] = r[1];
            bh[2*p+1][0] = r[2]; bh[2*p+1][1] = r[3];
            ldsm4(r, sb + OFF_BLO + boff);
            bl[2*p  ][0] = r[0]; bl[2*p  ][1] = r[1];
            bl[2*p+1][0] = r[2]; bl[2*p+1][1] = r[3];
        }
        #pragma unroll
        for (int t = 0; t < 4; t++){
            mma16816(acc[t], ah, bh[t]);
            mma16816(acc[t], al, bh[t]);
            mma16816(acc[t], ah, bl[t]);
        }
    }
}

// ---------------------------------------------------------------------------
// K_A: uber-GEMM. grid (128 rowtiles, 3 mats), 256 thr.
//   mat 0: m1z = z @ W1^T + b1          -> g_m1
//   mat 1: m2z = z @ W2^T + b2          -> g_m2x  (+ fused pair-max rows)
//   mat 2: p0  = z @ WuL^T  (no bias)   -> g_p
// ---------------------------------------------------------------------------
__global__ __launch_bounds__(256) void kA_gemm(
    const float* __restrict__ z,
    const float* __restrict__ W1, const float* __restrict__ b1,
    const float* __restrict__ W2, const float* __restrict__ b2,
    const float* __restrict__ Wu)
{
    extern __shared__ __align__(16) char sm[];
    const uint32_t sb = smem_to_u32(sm);
    const int tid  = threadIdx.x;
    const int wid  = tid >> 5, lane = tid & 31;
    const int wr   = wid >> 2, wc = wid & 3;
    const int row0 = blockIdx.x * 32;
    const int mat  = blockIdx.y;

    const float* W;  int ldw;
    if      (mat == 0){ W = W1; ldw = ZZ; }
    else if (mat == 1){ W = W2; ldw = ZZ; }
    else              { W = Wu; ldw = 2 * ZZ; }   // WuL = Wu[:, 0:128]

    if (tid < 128){
        float bias_v = 0.f;
        if (mat == 0) bias_v = __ldg(&b1[tid]);
        else if (mat == 1) bias_v = __ldg(&b2[tid]);
        ((float*)(sm + OFF_BIAS))[tid] = bias_v;
    }

    stage_rows(z + (size_t)row0 * ZZ, ZZ, 32, sm, OFF_AHI, OFF_ALO, tid);
    stage_rows(W, ldw, 128, sm, OFF_BHI, OFF_BLO, tid);
    __syncthreads();

    float acc[4][4];
    #pragma unroll
    for (int t = 0; t < 4; t++)
        #pragma unroll
        for (int c = 0; c < 4; c++) acc[t][c] = 0.f;

    compute_chunk8(sb, wr, wc, lane, acc);

    const float* bias = (const float*)(sm + OFF_BIAS);
    #pragma unroll
    for (int t = 0; t < 4; t++){
        int gn   = wc*32 + t*8 + (lane & 3)*2;
        int rlo  = row0 + wr*16 + (lane >> 2);
        float bx = bias[gn], by = bias[gn+1];
        float2 v0 = make_float2(acc[t][0] + bx, acc[t][1] + by);
        float2 v1 = make_float2(acc[t][2] + bx, acc[t][3] + by);
        if (mat == 0){
            *(float2*)(g_m1 + (size_t)rlo * ZZ + gn)       = v0;
            *(float2*)(g_m1 + (size_t)(rlo + 8) * ZZ + gn) = v1;
        } else if (mat == 1){
            int b0 = rlo >> 8,       i0 = rlo & 255;
            int b8 = (rlo + 8) >> 8, i8 = (rlo + 8) & 255;
            *(float2*)(g_m2x + ((size_t)b0 * M2P + i0) * ZZ + gn) = v0;
            *(float2*)(g_m2x + ((size_t)b8 * M2P + i8) * ZZ + gn) = v1;
        } else {
            *(float2*)(g_p + (size_t)rlo * HH + gn)       = v0;
            *(float2*)(g_p + (size_t)(rlo + 8) * HH + gn) = v1;
        }
    }

    // Fused k2a: this CTA owns 32 consecutive m2z rows = 16 complete pairs.
    if (mat == 1){
        __syncthreads();   // all m2z stores visible block-wide
        const int b   = row0 >> 8;
        const int il0 = row0 & 255;
        const float4* rows = (const float4*)g_m2x;
        #pragma unroll
        for (int f = tid; f < 512; f += 256){
            int pr = f >> 5, q = f & 31;
            int r0 = il0 + 2*pr;
            float4 a = rows[((size_t)b * M2P + r0    ) * 32 + q];
            float4 c = rows[((size_t)b * M2P + r0 + 1) * 32 + q];
            float4 m;
            m.x = fmaxf(a.x, c.x); m.y = fmaxf(a.y, c.y);
            m.z = fmaxf(a.z, c.z); m.w = fmaxf(a.w, c.w);
            ((float4*)g_m2x)[((size_t)b * M2P + 256 + (il0 >> 1) + pr) * 32 + q] = m;
        }
    }
}

// ---------------------------------------------------------------------------
// K2: m[b,i,:] = relu(m1z[b,i,:] + max_{j: P[b,j,i]!=0} m2z[b,j,:])
// Warp = one i. Pair-collapsed neighbor list, unroll-8 MLP loop.
// ---------------------------------------------------------------------------
__global__ __launch_bounds__(512) void k2_maxmsg(const int* __restrict__ P)
{
    __shared__ int PsT[16][257];
    __shared__ unsigned short lists[16][128];
    const int b   = blockIdx.y;
    const int i0  = blockIdx.x * 16;
    const int tid = threadIdx.x;

    for (int idx = tid; idx < KK * 16; idx += 512) {
        int j = idx >> 4, il = idx & 15;
        PsT[il][j] = P[(b * KK + j) * KK + i0 + il];
    }
    __syncthreads();

    const int w    = tid >> 5;
    const int lane = tid & 31;

    int cnt = 0;
    #pragma unroll
    for (int jb = 0; jb < 128; jb += 32) {
        int jp = jb + lane;
        int f0 = PsT[w][2*jp];
        int f1 = PsT[w][2*jp + 1];
        int present = (f0 | f1) != 0;
        int idx = (f0 && f1) ? (256 + jp) : (f0 ? 2*jp : 2*jp + 1);
        unsigned bal = __ballot_sync(0xffffffffu, present);
        if (present) {
            int pos = cnt + __popc(bal & ((1u << lane) - 1u));
            lists[w][pos] = (unsigned short)idx;
        }
        cnt += __popc(bal);
    }
    __syncwarp();

    const float* base = g_m2x + (size_t)b * M2P * ZZ + lane * 4;
    float4 acc = make_float4(-INFINITY, -INFINITY, -INFINITY, -INFINITY);

    int e = 0;
    for (; e + 8 <= cnt; e += 8) {
        ushort4 ja = *(const ushort4*)&lists[w][e];
        ushort4 jb = *(const ushort4*)&lists[w][e + 4];
        float4 v0 = *(const float4*)(base + (int)ja.x * ZZ);
        float4 v1 = *(const float4*)(base + (int)ja.y * ZZ);
        float4 v2 = *(const float4*)(base + (int)ja.z * ZZ);
        float4 v3 = *(const float4*)(base + (int)ja.w * ZZ);
        float4 v4 = *(const float4*)(base + (int)jb.x * ZZ);
        float4 v5 = *(const float4*)(base + (int)jb.y * ZZ);
        float4 v6 = *(const float4*)(base + (int)jb.z * ZZ);
        float4 v7 = *(const float4*)(base + (int)jb.w * ZZ);
        acc.x = fmaxf(acc.x, fmaxf(fmaxf(fmaxf(v0.x,v1.x),fmaxf(v2.x,v3.x)),
                                   fmaxf(fmaxf(v4.x,v5.x),fmaxf(v6.x,v7.x))));
        acc.y = fmaxf(acc.y, fmaxf(fmaxf(fmaxf(v0.y,v1.y),fmaxf(v2.y,v3.y)),
                                   fmaxf(fmaxf(v4.y,v5.y),fmaxf(v6.y,v7.y))));
        acc.z = fmaxf(acc.z, fmaxf(fmaxf(fmaxf(v0.z,v1.z),fmaxf(v2.z,v3.z)),
                                   fmaxf(fmaxf(v4.z,v5.z),fmaxf(v6.z,v7.z))));
        acc.w = fmaxf(acc.w, fmaxf(fmaxf(fmaxf(v0.w,v1.w),fmaxf(v2.w,v3.w)),
                                   fmaxf(fmaxf(v4.w,v5.w),fmaxf(v6.w,v7.w))));
    }
    for (; e + 4 <= cnt; e += 4) {
        ushort4 jj = *(const ushort4*)&lists[w][e];
        float4 v0 = *(const float4*)(base + (int)jj.x * ZZ);
        float4 v1 = *(const float4*)(base + (int)jj.y * ZZ);
        float4 v2 = *(const float4*)(base + (int)jj.z * ZZ);
        float4 v3 = *(const float4*)(base + (int)jj.w * ZZ);
        acc.x = fmaxf(fmaxf(fmaxf(acc.x, v0.x), fmaxf(v1.x, v2.x)), v3.x);
        acc.y = fmaxf(fmaxf(fmaxf(acc.y, v0.y), fmaxf(v1.y, v2.y)), v3.y);
        acc.z = fmaxf(fmaxf(fmaxf(acc.z, v0.z), fmaxf(v1.z, v2.z)), v3.z);
        acc.w = fmaxf(fmaxf(fmaxf(acc.w, v0.w), fmaxf(v1.w, v2.w)), v3.w);
    }
    for (; e < cnt; e++) {
        int j = lists[w][e];
        float4 v = *(const float4*)(base + j * ZZ);
        acc.x = fmaxf(acc.x, v.x);
        acc.y = fmaxf(acc.y, v.y);
        acc.z = fmaxf(acc.z, v.z);
        acc.w = fmaxf(acc.w, v.w);
    }

    const size_t off = ((size_t)b * KK + i0 + w) * ZZ + lane * 4;
    float4 m1 = *(const float4*)(g_m1 + off);
    float4 m;
    m.x = fmaxf(m1.x + acc.x, 0.f);
    m.y = fmaxf(m1.y + acc.y, 0.f);
    m.z = fmaxf(m1.z + acc.z, 0.f);
    m.w = fmaxf(m1.w + acc.w, 0.f);
    *(float4*)(g_m + off) = m;
}

// ---------------------------------------------------------------------------
// K_B: p1 = m @ WuR^T, fused epilogue: out = relu(p0 + p1 + bu).
// grid 128 rowtiles, 256 thr.
// ---------------------------------------------------------------------------
__global__ __launch_bounds__(256) void kB_gemm(
    const float* __restrict__ Wu, const float* __restrict__ bu,
    float* __restrict__ out)
{
    extern __shared__ __align__(16) char sm[];
    const uint32_t sb = smem_to_u32(sm);
    const int tid  = threadIdx.x;
    const int wid  = tid >> 5, lane = tid & 31;
    const int wr   = wid >> 2, wc = wid & 3;
    const int row0 = blockIdx.x * 32;

    if (tid < 128) ((float*)(sm + OFF_BIAS))[tid] = __ldg(&bu[tid]);
    stage_rows(g_m + (size_t)row0 * ZZ, ZZ, 32, sm, OFF_AHI, OFF_ALO, tid);
    stage_rows(Wu + ZZ, 2 * ZZ, 128, sm, OFF_BHI, OFF_BLO, tid);  // WuR
    __syncthreads();

    float acc[4][4];
    #pragma unroll
    for (int t = 0; t < 4; t++)
        #pragma unroll
        for (int c = 0; c < 4; c++) acc[t][c] = 0.f;

    compute_chunk8(sb, wr, wc, lane, acc);

    const float* bias = (const float*)(sm + OFF_BIAS);
    #pragma unroll
    for (int t = 0; t < 4; t++){
        int gn  = wc*32 + t*8 + (lane & 3)*2;
        int rlo = row0 + wr*16 + (lane >> 2);
        float bx = bias[gn], by = bias[gn+1];
        float2 p0a = *(const float2*)(g_p + (size_t)rlo * HH + gn);
        float2 p0b = *(const float2*)(g_p + (size_t)(rlo + 8) * HH + gn);
        float2 v0 = make_float2(fmaxf(acc[t][0] + p0a.x + bx, 0.f),
                                fmaxf(acc[t][1] + p0a.y + by, 0.f));
        float2 v1 = make_float2(fmaxf(acc[t][2] + p0b.x + bx, 0.f),
                                fmaxf(acc[t][3] + p0b.y + by, 0.f));
        *(float2*)(out + (size_t)rlo * HH + gn)       = v0;
        *(float2*)(out + (size_t)(rlo + 8) * HH + gn) = v1;
    }
}

// ---------------------------------------------------------------------------
extern "C" void kernel_launch(void* const* d_in, const int* in_sizes, int n_in,
                              void* d_out, int out_size)
{
    const float* z  = (const float*)d_in[0];
    const int*   P  = (const int*)  d_in[1];
    const float* W1 = (const float*)d_in[2];
    const float* b1 = (const float*)d_in[3];
    const float* W2 = (const float*)d_in[4];
    const float* b2 = (const float*)d_in[5];
    const float* Wu = (const float*)d_in[6];
    const float* bu = (const float*)d_in[7];
    float* out = (float*)d_out;

    cudaFuncSetAttribute(kA_gemm, cudaFuncAttributeMaxDynamicSharedMemorySize, SMEM_BYTES);
    cudaFuncSetAttribute(kB_gemm, cudaFuncAttributeMaxDynamicSharedMemorySize, SMEM_BYTES);

    kA_gemm<<<dim3(BB * KK / 32, 3), 256, SMEM_BYTES>>>(z, W1, b1, W2, b2, Wu);
    k2_maxmsg<<<dim3(KK / 16, BB), 512>>>(P);
    kB_gemm<<<BB * KK / 32, 256, SMEM_BYTES>>>(Wu, bu, out);
}

// round 16
// speedup vs baseline: 1.4744x; 1.1742x over previous
#include <cuda_runtime.h>
#include <cuda_bf16.h>
#include <math.h>
#include <cstdint>

#define BB 16
#define KK 256
#define ZZ 128
#define HH 128
#define M2P 384   // padded rows per batch in g_m2x: 256 m2z rows + 128 pair-max rows

typedef unsigned short ushortt;

// Scratch (allocation-free rule: __device__ globals)
__device__ float g_m1 [BB*KK*ZZ];    // m1z
__device__ float g_m2x[BB*M2P*ZZ];   // rows 0..255: m2z ; rows 256..383: pair-max
__device__ float g_m  [BB*KK*ZZ];    // relu(m1z + masked max)
__device__ float g_p  [BB*KK*HH];    // p0 = z @ WuL^T partial
// Pre-split weights, 4 blocks of [128][128] halves: W1, W2, WuL, WuR
__device__ ushortt g_wbh[4*ZZ*ZZ];
__device__ ushortt g_wbl[4*ZZ*ZZ];

// ===========================================================================
// mma.sync bf16 GEMM infrastructure (arch-stable: sm_80+, works at compute_103)
// Tile: 32 rows x 128 cols, K=128 chunk resident as bf16 hi+lo. 256 threads.
// ===========================================================================
#define LDH 136            // smem stride in halves (128 + 8 pad -> ldmatrix conflict-free)
#define OFF_BIAS 0                        // 512 B
#define OFF_AHI  512                      // 32 x 136 halves = 8704 B
#define OFF_ALO  (OFF_AHI + 32*LDH*2)
#define OFF_BHI  (OFF_ALO + 32*LDH*2)     // 128 x 136 halves = 34816 B
#define OFF_BLO  (OFF_BHI + 128*LDH*2)
#define SMEM_BYTES (OFF_BLO + 128*LDH*2)  // 87552 B -> 2 CTAs/SM (16 warps/SM)

__device__ __forceinline__ uint32_t smem_to_u32(const void* p){
    uint32_t a;
    asm("{ .reg .u64 t; cvta.to.shared.u64 t, %1; cvt.u32.u64 %0, t; }"
        : "=r"(a) : "l"(p));
    return a;
}
__device__ __forceinline__ void ldsm4(uint32_t* r, uint32_t a){
    asm volatile("ldmatrix.sync.aligned.m8n8.x4.shared.b16 {%0,%1,%2,%3}, [%4];"
        : "=r"(r[0]), "=r"(r[1]), "=r"(r[2]), "=r"(r[3]) : "r"(a));
}
__device__ __forceinline__ void mma16816(float* c, const uint32_t* a, const uint32_t* b){
    asm volatile(
        "mma.sync.aligned.m16n8k16.row.col.f32.bf16.bf16.f32 "
        "{%0,%1,%2,%3}, {%4,%5,%6,%7}, {%8,%9}, {%0,%1,%2,%3};"
        : "+f"(c[0]), "+f"(c[1]), "+f"(c[2]), "+f"(c[3])
        : "r"(a[0]), "r"(a[1]), "r"(a[2]), "r"(a[3]), "r"(b[0]), "r"(b[1]));
}
#define CP16(dst, src) \
    asm volatile("cp.async.cg.shared.global [%0], [%1], 16;" \
                 :: "r"(dst), "l"(src) : "memory")
#define CP_COMMIT() asm volatile("cp.async.commit_group;" ::: "memory")
#define CP_WAIT0()  asm volatile("cp.async.wait_group 0;"  ::: "memory")

// f32x4 -> bf16 hi/lo packed pairs
__device__ __forceinline__ void split4(float4 v, uint2 &hv, uint2 &lv){
    __nv_bfloat162 h0 = __floats2bfloat162_rn(v.x, v.y);
    __nv_bfloat162 h1 = __floats2bfloat162_rn(v.z, v.w);
    float l0 = v.x - __bfloat162float(h0.x);
    float l1 = v.y - __bfloat162float(h0.y);
    float l2 = v.z - __bfloat162float(h1.x);
    float l3 = v.w - __bfloat162float(h1.y);
    __nv_bfloat162 g0 = __floats2bfloat162_rn(l0, l1);
    __nv_bfloat162 g1 = __floats2bfloat162_rn(l2, l3);
    hv.x = *(uint32_t*)&h0; hv.y = *(uint32_t*)&h1;
    lv.x = *(uint32_t*)&g0; lv.y = *(uint32_t*)&g1;
}

// Stage rows x 128 f32 tile -> bf16 hi + lo, row-major [row][LDH] halves.
__device__ __forceinline__ void stage_rows(
    const float* __restrict__ src, int ldf, int rows,
    char* sm, int off_hi, int off_lo, int tid)
{
    for (int f = tid; f < rows * 32; f += 256){
        int r  = f >> 5;
        int c4 = f & 31;
        float4 v = *(const float4*)(src + (size_t)r * ldf + 4*c4);
        uint2 hv, lv; split4(v, hv, lv);
        uint32_t byt = (uint32_t)(r * LDH + 4*c4) * 2u;
        *(uint2*)(sm + off_hi + byt) = hv;
        *(uint2*)(sm + off_lo + byt) = lv;
    }
}

// Async-stage the pre-split 128x128-half B tile (hi+lo) into padded smem.
// 2048 16B chunks per buffer / 256 thr = 8 iters x 2 cp.async, no registers.
__device__ __forceinline__ void stage_B_async(
    const ushortt* __restrict__ gh, const ushortt* __restrict__ gl,
    uint32_t sb, int tid)
{
    #pragma unroll
    for (int f = tid; f < 2048; f += 256){
        int r = f >> 4, c = f & 15;
        CP16(sb + OFF_BHI + (uint32_t)r * (LDH*2) + c*16,
             (const void*)(gh + (size_t)r * ZZ + c*8));
        CP16(sb + OFF_BLO + (uint32_t)r * (LDH*2) + c*16,
             (const void*)(gl + (size_t)r * ZZ + c*8));
    }
}

// 8 k-steps over the staged K=128 chunk; 8 warps.
// Warp tile 16 rows x 32 cols: wr = wid>>2 (0..1), wc = wid&3 (0..3).
// acc[4][4] accumulates split terms AhBh + AlBh + AhBl.
__device__ __forceinline__ void compute_chunk8(
    uint32_t sb, int wr, int wc, int lane, float acc[4][4])
{
    #pragma unroll
    for (int ks = 0; ks < 8; ks++){
        const int k0 = ks * 16;
        uint32_t ah[4], al[4];
        {
            int arow = wr*16 + (lane & 15);
            int acol = k0 + 8*(lane >> 4);
            uint32_t aoff = (uint32_t)(arow * LDH + acol) * 2u;
            ldsm4(ah, sb + OFF_AHI + aoff);
            ldsm4(al, sb + OFF_ALO + aoff);
        }
        uint32_t bh[4][2], bl[4][2];
        #pragma unroll
        for (int p = 0; p < 2; p++){
            int brow = wc*32 + p*16 + (lane & 7) + ((lane >> 4) & 1)*8;
            int bcol = k0 + ((lane >> 3) & 1)*8;
            uint32_t boff = (uint32_t)(brow * LDH + bcol) * 2u;
            uint32_t r[4];
            ldsm4(r, sb + OFF_BHI + boff);
            bh[2*p  ][0] = r[0]; bh[2*p  ][1] = r[1];
            bh[2*p+1][0] = r[2]; bh[2*p+1][1] = r[3];
            ldsm4(r, sb + OFF_BLO + boff);
            bl[2*p  ][0] = r[0]; bl[2*p  ][1] = r[1];
            bl[2*p+1][0] = r[2]; bl[2*p+1][1] = r[3];
        }
        #pragma unroll
        for (int t = 0; t < 4; t++){
            mma16816(acc[t], ah, bh[t]);
            mma16816(acc[t], al, bh[t]);
            mma16816(acc[t], ah, bl[t]);
        }
    }
}

// ---------------------------------------------------------------------------
// KPREP: split W1, W2, WuL, WuR into bf16 hi/lo blocks [blk][128][128].
// 16384 float4 groups; 64 CTAs x 256 thr.
// ---------------------------------------------------------------------------
__global__ __launch_bounds__(256) void kprep(
    const float* __restrict__ W1, const float* __restrict__ W2,
    const float* __restrict__ Wu)
{
    int t   = blockIdx.x * 256 + threadIdx.x;   // 0..16383
    int blk = t >> 12;
    int r   = (t >> 5) & 127;
    int c4  = t & 31;
    const float* src;
    if      (blk == 0) src = W1 + r * ZZ + 4*c4;
    else if (blk == 1) src = W2 + r * ZZ + 4*c4;
    else if (blk == 2) src = Wu + r * 2*ZZ + 4*c4;          // WuL
    else               src = Wu + r * 2*ZZ + ZZ + 4*c4;     // WuR
    float4 v = *(const float4*)src;
    uint2 hv, lv; split4(v, hv, lv);
    ((uint2*)g_wbh)[t] = hv;
    ((uint2*)g_wbl)[t] = lv;
}

// ---------------------------------------------------------------------------
// K_A: uber-GEMM. grid (128 rowtiles, 3 mats), 256 thr.
//   mat 0: m1z = z @ W1^T + b1          -> g_m1
//   mat 1: m2z = z @ W2^T + b2          -> g_m2x  (+ fused pair-max rows)
//   mat 2: p0  = z @ WuL^T  (no bias)   -> g_p
// B comes pre-split via cp.async; A converted in-kernel (4 iters/thread).
// ---------------------------------------------------------------------------
__global__ __launch_bounds__(256) void kA_gemm(
    const float* __restrict__ z,
    const float* __restrict__ b1, const float* __restrict__ b2)
{
    extern __shared__ __align__(16) char sm[];
    const uint32_t sb = smem_to_u32(sm);
    const int tid  = threadIdx.x;
    const int wid  = tid >> 5, lane = tid & 31;
    const int wr   = wid >> 2, wc = wid & 3;
    const int row0 = blockIdx.x * 32;
    const int mat  = blockIdx.y;

    // B staging: fire-and-forget async copies of the pre-split weight block.
    stage_B_async(g_wbh + (size_t)mat * ZZ * ZZ,
                  g_wbl + (size_t)mat * ZZ * ZZ, sb, tid);
    CP_COMMIT();

    if (tid < 128){
        float bias_v = 0.f;
        if (mat == 0) bias_v = __ldg(&b1[tid]);
        else if (mat == 1) bias_v = __ldg(&b2[tid]);
        ((float*)(sm + OFF_BIAS))[tid] = bias_v;
    }

    // A staging (overlaps the in-flight B copies).
    stage_rows(z + (size_t)row0 * ZZ, ZZ, 32, sm, OFF_AHI, OFF_ALO, tid);
    CP_WAIT0();
    __syncthreads();

    float acc[4][4];
    #pragma unroll
    for (int t = 0; t < 4; t++)
        #pragma unroll
        for (int c = 0; c < 4; c++) acc[t][c] = 0.f;

    compute_chunk8(sb, wr, wc, lane, acc);

    const float* bias = (const float*)(sm + OFF_BIAS);
    #pragma unroll
    for (int t = 0; t < 4; t++){
        int gn   = wc*32 + t*8 + (lane & 3)*2;
        int rlo  = row0 + wr*16 + (lane >> 2);
        float bx = bias[gn], by = bias[gn+1];
        float2 v0 = make_float2(acc[t][0] + bx, acc[t][1] + by);
        float2 v1 = make_float2(acc[t][2] + bx, acc[t][3] + by);
        if (mat == 0){
            *(float2*)(g_m1 + (size_t)rlo * ZZ + gn)       = v0;
            *(float2*)(g_m1 + (size_t)(rlo + 8) * ZZ + gn) = v1;
        } else if (mat == 1){
            int b0 = rlo >> 8,       i0 = rlo & 255;
            int b8 = (rlo + 8) >> 8, i8 = (rlo + 8) & 255;
            *(float2*)(g_m2x + ((size_t)b0 * M2P + i0) * ZZ + gn) = v0;
            *(float2*)(g_m2x + ((size_t)b8 * M2P + i8) * ZZ + gn) = v1;
        } else {
            *(float2*)(g_p + (size_t)rlo * HH + gn)       = v0;
            *(float2*)(g_p + (size_t)(rlo + 8) * HH + gn) = v1;
        }
    }

    // Fused k2a: this CTA owns 32 consecutive m2z rows = 16 complete pairs.
    if (mat == 1){
        __syncthreads();   // all m2z stores visible block-wide
        const int b   = row0 >> 8;
        const int il0 = row0 & 255;
        const float4* rows = (const float4*)g_m2x;
        #pragma unroll
        for (int f = tid; f < 512; f += 256){
            int pr = f >> 5, q = f & 31;
            int r0 = il0 + 2*pr;
            float4 a = rows[((size_t)b * M2P + r0    ) * 32 + q];
            float4 c = rows[((size_t)b * M2P + r0 + 1) * 32 + q];
            float4 m;
            m.x = fmaxf(a.x, c.x); m.y = fmaxf(a.y, c.y);
            m.z = fmaxf(a.z, c.z); m.w = fmaxf(a.w, c.w);
            ((float4*)g_m2x)[((size_t)b * M2P + 256 + (il0 >> 1) + pr) * 32 + q] = m;
        }
    }
}

// ---------------------------------------------------------------------------
// K2: m[b,i,:] = relu(m1z[b,i,:] + max_{j: P[b,j,i]!=0} m2z[b,j,:])
// Warp = one i. Pair-collapsed neighbor list, unroll-8 MLP loop.
// ---------------------------------------------------------------------------
__global__ __launch_bounds__(512) void k2_maxmsg(const int* __restrict__ P)
{
    __shared__ int PsT[16][257];
    __shared__ unsigned short lists[16][128];
    const int b   = blockIdx.y;
    const int i0  = blockIdx.x * 16;
    const int tid = threadIdx.x;

    for (int idx = tid; idx < KK * 16; idx += 512) {
        int j = idx >> 4, il = idx & 15;
        PsT[il][j] = P[(b * KK + j) * KK + i0 + il];
    }
    __syncthreads();

    const int w    = tid >> 5;
    const int lane = tid & 31;

    int cnt = 0;
    #pragma unroll
    for (int jb = 0; jb < 128; jb += 32) {
        int jp = jb + lane;
        int f0 = PsT[w][2*jp];
        int f1 = PsT[w][2*jp + 1];
        int present = (f0 | f1) != 0;
        int idx = (f0 && f1) ? (256 + jp) : (f0 ? 2*jp : 2*jp + 1);
        unsigned bal = __ballot_sync(0xffffffffu, present);
        if (present) {
            int pos = cnt + __popc(bal & ((1u << lane) - 1u));
            lists[w][pos] = (unsigned short)idx;
        }
        cnt += __popc(bal);
    }
    __syncwarp();

    const float* base = g_m2x + (size_t)b * M2P * ZZ + lane * 4;
    float4 acc = make_float4(-INFINITY, -INFINITY, -INFINITY, -INFINITY);

    int e = 0;
    for (; e + 8 <= cnt; e += 8) {
        ushort4 ja = *(const ushort4*)&lists[w][e];
        ushort4 jb = *(const ushort4*)&lists[w][e + 4];
        float4 v0 = *(const float4*)(base + (int)ja.x * ZZ);
        float4 v1 = *(const float4*)(base + (int)ja.y * ZZ);
        float4 v2 = *(const float4*)(base + (int)ja.z * ZZ);
        float4 v3 = *(const float4*)(base + (int)ja.w * ZZ);
        float4 v4 = *(const float4*)(base + (int)jb.x * ZZ);
        float4 v5 = *(const float4*)(base + (int)jb.y * ZZ);
        float4 v6 = *(const float4*)(base + (int)jb.z * ZZ);
        float4 v7 = *(const float4*)(base + (int)jb.w * ZZ);
        acc.x = fmaxf(acc.x, fmaxf(fmaxf(fmaxf(v0.x,v1.x),fmaxf(v2.x,v3.x)),
                                   fmaxf(fmaxf(v4.x,v5.x),fmaxf(v6.x,v7.x))));
        acc.y = fmaxf(acc.y, fmaxf(fmaxf(fmaxf(v0.y,v1.y),fmaxf(v2.y,v3.y)),
                                   fmaxf(fmaxf(v4.y,v5.y),fmaxf(v6.y,v7.y))));
        acc.z = fmaxf(acc.z, fmaxf(fmaxf(fmaxf(v0.z,v1.z),fmaxf(v2.z,v3.z)),
                                   fmaxf(fmaxf(v4.z,v5.z),fmaxf(v6.z,v7.z))));
        acc.w = fmaxf(acc.w, fmaxf(fmaxf(fmaxf(v0.w,v1.w),fmaxf(v2.w,v3.w)),
                                   fmaxf(fmaxf(v4.w,v5.w),fmaxf(v6.w,v7.w))));
    }
    for (; e + 4 <= cnt; e += 4) {
        ushort4 jj = *(const ushort4*)&lists[w][e];
        float4 v0 = *(const float4*)(base + (int)jj.x * ZZ);
        float4 v1 = *(const float4*)(base + (int)jj.y * ZZ);
        float4 v2 = *(const float4*)(base + (int)jj.z * ZZ);
        float4 v3 = *(const float4*)(base + (int)jj.w * ZZ);
        acc.x = fmaxf(fmaxf(fmaxf(acc.x, v0.x), fmaxf(v1.x, v2.x)), v3.x);
        acc.y = fmaxf(fmaxf(fmaxf(acc.y, v0.y), fmaxf(v1.y, v2.y)), v3.y);
        acc.z = fmaxf(fmaxf(fmaxf(acc.z, v0.z), fmaxf(v1.z, v2.z)), v3.z);
        acc.w = fmaxf(fmaxf(fmaxf(acc.w, v0.w), fmaxf(v1.w, v2.w)), v3.w);
    }
    for (; e < cnt; e++) {
        int j = lists[w][e];
        float4 v = *(const float4*)(base + j * ZZ);
        acc.x = fmaxf(acc.x, v.x);
        acc.y = fmaxf(acc.y, v.y);
        acc.z = fmaxf(acc.z, v.z);
        acc.w = fmaxf(acc.w, v.w);
    }

    const size_t off = ((size_t)b * KK + i0 + w) * ZZ + lane * 4;
    float4 m1 = *(const float4*)(g_m1 + off);
    float4 m;
    m.x = fmaxf(m1.x + acc.x, 0.f);
    m.y = fmaxf(m1.y + acc.y, 0.f);
    m.z = fmaxf(m1.z + acc.z, 0.f);
    m.w = fmaxf(m1.w + acc.w, 0.f);
    *(float4*)(g_m + off) = m;
}

// ---------------------------------------------------------------------------
// K_B: p1 = m @ WuR^T, fused epilogue: out = relu(p0 + p1 + bu).
// grid 128 rowtiles, 256 thr. B = pre-split block 3 via cp.async.
// ---------------------------------------------------------------------------
__global__ __launch_bounds__(256) void kB_gemm(
    const float* __restrict__ bu, float* __restrict__ out)
{
    extern __shared__ __align__(16) char sm[];
    const uint32_t sb = smem_to_u32(sm);
    const int tid  = threadIdx.x;
    const int wid  = tid >> 5, lane = tid & 31;
    const int wr   = wid >> 2, wc = wid & 3;
    const int row0 = blockIdx.x * 32;

    stage_B_async(g_wbh + (size_t)3 * ZZ * ZZ,
                  g_wbl + (size_t)3 * ZZ * ZZ, sb, tid);
    CP_COMMIT();

    if (tid < 128) ((float*)(sm + OFF_BIAS))[tid] = __ldg(&bu[tid]);
    stage_rows(g_m + (size_t)row0 * ZZ, ZZ, 32, sm, OFF_AHI, OFF_ALO, tid);
    CP_WAIT0();
    __syncthreads();

    float acc[4][4];
    #pragma unroll
    for (int t = 0; t < 4; t++)
        #pragma unroll
        for (int c = 0; c < 4; c++) acc[t][c] = 0.f;

    compute_chunk8(sb, wr, wc, lane, acc);

    const float* bias = (const float*)(sm + OFF_BIAS);
    #pragma unroll
    for (int t = 0; t < 4; t++){
        int gn  = wc*32 + t*8 + (lane & 3)*2;
        int rlo = row0 + wr*16 + (lane >> 2);
        float bx = bias[gn], by = bias[gn+1];
        float2 p0a = *(const float2*)(g_p + (size_t)rlo * HH + gn);
        float2 p0b = *(const float2*)(g_p + (size_t)(rlo + 8) * HH + gn);
        float2 v0 = make_float2(fmaxf(acc[t][0] + p0a.x + bx, 0.f),
                                fmaxf(acc[t][1] + p0a.y + by, 0.f));
        float2 v1 = make_float2(fmaxf(acc[t][2] + p0b.x + bx, 0.f),
                                fmaxf(acc[t][3] + p0b.y + by, 0.f));
        *(float2*)(out + (size_t)rlo * HH + gn)       = v0;
        *(float2*)(out + (size_t)(rlo + 8) * HH + gn) = v1;
    }
}

// ---------------------------------------------------------------------------
extern "C" void kernel_launch(void* const* d_in, const int* in_sizes, int n_in,
                              void* d_out, int out_size)
{
    const float* z  = (const float*)d_in[0];
    const int*   P  = (const int*)  d_in[1];
    const float* W1 = (const float*)d_in[2];
    const float* b1 = (const float*)d_in[3];
    const float* W2 = (const float*)d_in[4];
    const float* b2 = (const float*)d_in[5];
    const float* Wu = (const float*)d_in[6];
    const float* bu = (const float*)d_in[7];
    float* out = (float*)d_out;

    cudaFuncSetAttribute(kA_gemm, cudaFuncAttributeMaxDynamicSharedMemorySize, SMEM_BYTES);
    cudaFuncSetAttribute(kB_gemm, cudaFuncAttributeMaxDynamicSharedMemorySize, SMEM_BYTES);

    kprep<<<64, 256>>>(W1, W2, Wu);
    kA_gemm<<<dim3(BB * KK / 32, 3), 256, SMEM_BYTES>>>(z, b1, b2);
    k2_maxmsg<<<dim3(KK / 16, BB), 512>>>(P);
    kB_gemm<<<BB * KK / 32, 256, SMEM_BYTES>>>(bu, out);
}